// round 13
// baseline (speedup 1.0000x reference)
#include <cuda_runtime.h>
#include <cuda_bf16.h>
#include <cstdint>
#include <math.h>

// ---- problem constants ----
#define NUM_ENT 100000
#define BATCH   4096
#define NROWS   8192         // 2*BATCH rows of H = [h1; h2]
#define DIM     768
#define NB      64           // NROWS / 128 tile grid
#define NCHUNK  12           // DIM / 64
#define C_OFF   20.0f
#define INV_TAU 20.0f

#define SMSTRIDE 144                 // 64 bf16 (128B) + 16B pad -> ldmatrix conflict-free
#define TILEBYTES (128 * SMSTRIDE)   // 18432 B per matrix tile
#define STAGEBYTES (2 * TILEBYTES)   // A + B per stage = 36864
#define NSTAGE  3
#define SMEM_TOTAL (NSTAGE * STAGEBYTES)  // 110592 B (2 CTAs/SM = 221 KB)

// ---- device scratch ----
__device__ __align__(16) __nv_bfloat16 g_Hb[(size_t)NROWS * DIM];  // 12.6 MB
__device__ float g_S[NROWS];
__device__ float g_D[BATCH];

__device__ __forceinline__ uint32_t smem_u32(const void* p) {
    uint32_t a;
    asm("{ .reg .u64 t; cvta.to.shared.u64 t, %1; cvt.u32.u64 %0, t; }" : "=r"(a) : "l"(p));
    return a;
}
__device__ __forceinline__ void ldsm_x4(uint32_t& r0, uint32_t& r1, uint32_t& r2, uint32_t& r3,
                                        uint32_t addr) {
    asm volatile("ldmatrix.sync.aligned.m8n8.x4.shared.b16 {%0,%1,%2,%3}, [%4];"
                 : "=r"(r0), "=r"(r1), "=r"(r2), "=r"(r3) : "r"(addr));
}
__device__ __forceinline__ void mma_bf16(float* c, const uint32_t* a, uint32_t b0, uint32_t b1) {
    asm volatile(
        "mma.sync.aligned.m16n8k16.row.col.f32.bf16.bf16.f32 "
        "{%0,%1,%2,%3}, {%4,%5,%6,%7}, {%8,%9}, {%0,%1,%2,%3};"
        : "+f"(c[0]), "+f"(c[1]), "+f"(c[2]), "+f"(c[3])
        : "r"(a[0]), "r"(a[1]), "r"(a[2]), "r"(a[3]), "r"(b0), "r"(b1));
}
__device__ __forceinline__ void cp16(uint32_t dst, const void* src) {
    asm volatile("cp.async.cg.shared.global [%0], [%1], 16;" :: "r"(dst), "l"(src));
}

// ---------------- K1: warp-per-row gather + L2-normalize -> bf16 H, zero S ----------------
__global__ void k_normalize(const float* __restrict__ emb,
                            const int* __restrict__ links) {
    const int r = (blockIdx.x << 2) | (threadIdx.x >> 5);   // 4 rows per 128-thread block
    const int lane = threadIdx.x & 31;
    if (threadIdx.x < 4) g_S[(blockIdx.x << 2) + threadIdx.x] = 0.f;  // re-zero each replay

    int ent = (r < BATCH) ? links[2 * r] : links[2 * (r - BATCH) + 1];
    if (ent < 0) ent = 0;
    if (ent >= NUM_ENT) ent = NUM_ENT - 1;
    const float4* src = (const float4*)(emb + (size_t)ent * DIM);  // 192 float4s

    float4 v[6];
    float ss = 0.f;
#pragma unroll
    for (int j = 0; j < 6; j++) {
        v[j] = src[lane + j * 32];
        ss += v[j].x * v[j].x + v[j].y * v[j].y + v[j].z * v[j].z + v[j].w * v[j].w;
    }
#pragma unroll
    for (int o = 16; o; o >>= 1) ss += __shfl_xor_sync(0xffffffffu, ss, o);
    const float inv = rsqrtf(ss);

    uint2* dst = (uint2*)(g_Hb + (size_t)r * DIM);  // 4 bf16 per uint2
#pragma unroll
    for (int j = 0; j < 6; j++) {
        __nv_bfloat162 lo = __floats2bfloat162_rn(v[j].x * inv, v[j].y * inv);
        __nv_bfloat162 hi = __floats2bfloat162_rn(v[j].z * inv, v[j].w * inv);
        uint2 pk;
        pk.x = *(uint32_t*)&lo;
        pk.y = *(uint32_t*)&hi;
        dst[lane + j * 32] = pk;
    }
}

// ---------------- K2: triangular 128x128 tiles, 4 warps x (64x64), 3-stage pipeline ----------------
__global__ void __launch_bounds__(128, 2) k_gram() {
    extern __shared__ __align__(16) char smem[];
    const uint32_t sb = smem_u32(smem);

    // Closed-form linear id -> upper-triangular (bi, bj), bi <= bj < NB.
    const float fidx = (float)blockIdx.x;
    int bi = (int)((2.0f * NB + 1.0f - sqrtf((2.0f * NB + 1.0f) * (2.0f * NB + 1.0f)
                                             - 8.0f * fidx)) * 0.5f);
    if (bi < 0) bi = 0;
    if (bi > NB - 1) bi = NB - 1;
    while (bi > 0 && (int)blockIdx.x < bi * NB - (bi * (bi - 1)) / 2) bi--;
    while (bi < NB - 1 && (int)blockIdx.x >= (bi + 1) * NB - ((bi + 1) * bi) / 2) bi++;
    const int bj = bi + ((int)blockIdx.x - (bi * NB - (bi * (bi - 1)) / 2));

    const int rowBase = bi * 128;
    const int colBase = bj * 128;
    const int tid = threadIdx.x, wid = tid >> 5, lid = tid & 31;
    const int wm = (wid >> 1) * 64;   // warp m-offset (0 or 64)
    const int wn = (wid & 1) * 64;    // warp n-offset (0 or 64)

    const char* gA = (const char*)(g_Hb + (size_t)rowBase * DIM);  // 1536 B per row
    const char* gB = (const char*)(g_Hb + (size_t)colBase * DIM);

    // per-thread load coords (8 x 16B per matrix per chunk, 128 threads)
    int lrow[8], lq[8];
#pragma unroll
    for (int i = 0; i < 8; i++) {
        int idx = tid + i * 128;       // 0..1023
        lrow[i] = idx >> 3;
        lq[i] = (idx & 7) * 16;
    }

    // prologue: prefetch chunks 0,1 into stages 0,1
#pragma unroll
    for (int p = 0; p < 2; p++) {
        const uint32_t st = sb + p * STAGEBYTES;
        const int off = p * 128;
#pragma unroll
        for (int i = 0; i < 8; i++) {
            cp16(st + lrow[i] * SMSTRIDE + lq[i], gA + (size_t)lrow[i] * 1536 + off + lq[i]);
            cp16(st + TILEBYTES + lrow[i] * SMSTRIDE + lq[i],
                 gB + (size_t)lrow[i] * 1536 + off + lq[i]);
        }
        asm volatile("cp.async.commit_group;" ::: "memory");
    }

    float c[4][8][4];   // [am 16-row][an 8-col][quad]
#pragma unroll
    for (int am = 0; am < 4; am++)
#pragma unroll
        for (int an = 0; an < 8; an++)
#pragma unroll
            for (int q = 0; q < 4; q++) c[am][an][q] = 0.f;

    int stage = 0;
    for (int ch = 0; ch < NCHUNK; ch++) {
        // stage `stage` holds chunk ch (in flight); one group per chunk.
        if (ch < NCHUNK - 1)
            asm volatile("cp.async.wait_group 1;" ::: "memory");
        else
            asm volatile("cp.async.wait_group 0;" ::: "memory");
        __syncthreads();  // (a) chunk ch visible; (b) all warps done with chunk ch-1's stage

        // prefetch chunk ch+2 into the stage chunk ch-1 used (safe after the barrier)
        if (ch + 2 < NCHUNK) {
            const int ns = (stage + 2) % NSTAGE;
            const uint32_t st = sb + ns * STAGEBYTES;
            const int off = (ch + 2) * 128;
#pragma unroll
            for (int i = 0; i < 8; i++) {
                cp16(st + lrow[i] * SMSTRIDE + lq[i],
                     gA + (size_t)lrow[i] * 1536 + off + lq[i]);
                cp16(st + TILEBYTES + lrow[i] * SMSTRIDE + lq[i],
                     gB + (size_t)lrow[i] * 1536 + off + lq[i]);
            }
            asm volatile("cp.async.commit_group;" ::: "memory");
        }

        const uint32_t sbA = sb + stage * STAGEBYTES;
        const uint32_t sbB = sbA + TILEBYTES;

#pragma unroll
        for (int kh = 0; kh < 2; kh++) {   // two 32-wide k halves
            uint32_t bfr[8][4];
#pragma unroll
            for (int an = 0; an < 8; an++) {
                int n = wn + an * 8 + (lid & 7);
                uint32_t addr = sbB + n * SMSTRIDE + kh * 64 + ((lid >> 3) & 3) * 16;
                ldsm_x4(bfr[an][0], bfr[an][1], bfr[an][2], bfr[an][3], addr);
            }
#pragma unroll
            for (int k2 = 0; k2 < 2; k2++) {  // kstep = kh*2 + k2 (16 wide)
                uint32_t afr[4][4];
#pragma unroll
                for (int am = 0; am < 4; am++) {
                    int row = wm + am * 16 + (lid & 15);
                    uint32_t addr = sbA + row * SMSTRIDE + (kh * 2 + k2) * 32 + (lid >> 4) * 16;
                    ldsm_x4(afr[am][0], afr[am][1], afr[am][2], afr[am][3], addr);
                }
#pragma unroll
                for (int am = 0; am < 4; am++)
#pragma unroll
                    for (int an = 0; an < 8; an++)
                        mma_bf16(c[am][an], afr[am], bfr[an][k2 * 2], bfr[an][k2 * 2 + 1]);
            }
        }
        stage = (stage + 1) % NSTAGE;
    }

    // ---- Epilogue: scale, diag capture, exp (self-excluded), row & col sums ----
    float rs[8];    // row sums: [am*2 + half]
    float cs[16];   // col sums: [an*2 + subcol]
#pragma unroll
    for (int i = 0; i < 8; i++) rs[i] = 0.f;
#pragma unroll
    for (int i = 0; i < 16; i++) cs[i] = 0.f;

#pragma unroll
    for (int am = 0; am < 4; am++) {
        int rG0 = rowBase + wm + am * 16 + (lid >> 2);
#pragma unroll
        for (int an = 0; an < 8; an++) {
            int cG0 = colBase + wn + an * 8 + (lid & 3) * 2;
#pragma unroll
            for (int q = 0; q < 4; q++) {
                int rG = rG0 + (q >> 1) * 8;
                int cG = cG0 + (q & 1);
                float val = c[am][an][q] * INV_TAU;
                if (cG == rG + BATCH) g_D[rG] = val;  // diag of logits_ab
                float e = (rG == cG) ? 0.f : __expf(val - C_OFF);
                rs[am * 2 + (q >> 1)] += e;
                cs[an * 2 + (q & 1)] += e;
            }
        }
    }

    // Row reduce across the quad (lanes differing in lid&3 hold same rows)
#pragma unroll
    for (int i = 0; i < 8; i++) {
        rs[i] += __shfl_xor_sync(0xffffffffu, rs[i], 1);
        rs[i] += __shfl_xor_sync(0xffffffffu, rs[i], 2);
    }
    if ((lid & 3) == 0) {
#pragma unroll
        for (int am = 0; am < 4; am++)
#pragma unroll
            for (int h = 0; h < 2; h++)
                atomicAdd(&g_S[rowBase + wm + am * 16 + (lid >> 2) + h * 8],
                          rs[am * 2 + h]);
    }

    // Col reduce across groups (lanes differing in lid>>2 hold same cols); symmetry term
    if (bi != bj) {
#pragma unroll
        for (int i = 0; i < 16; i++) {
            cs[i] += __shfl_xor_sync(0xffffffffu, cs[i], 4);
            cs[i] += __shfl_xor_sync(0xffffffffu, cs[i], 8);
            cs[i] += __shfl_xor_sync(0xffffffffu, cs[i], 16);
        }
        if (lid < 4) {
#pragma unroll
            for (int an = 0; an < 8; an++)
#pragma unroll
                for (int s = 0; s < 2; s++)
                    atomicAdd(&g_S[colBase + wn + an * 8 + lid * 2 + s],
                              cs[an * 2 + s]);
        }
    }
}

// ---------------- K3: final loss reduction ----------------
__global__ void k_finalize(float* __restrict__ out) {
    float acc = 0.f;
    for (int i = threadIdx.x; i < BATCH; i += 256) {
        float lse_a = C_OFF + logf(g_S[i]);
        float lse_b = C_OFF + logf(g_S[BATCH + i]);
        acc += 0.5f * (lse_a + lse_b) - g_D[i];  // ALPHA = 0.5
    }
#pragma unroll
    for (int o = 16; o; o >>= 1) acc += __shfl_xor_sync(0xffffffffu, acc, o);
    __shared__ float ws[8];
    if ((threadIdx.x & 31) == 0) ws[threadIdx.x >> 5] = acc;
    __syncthreads();
    if (threadIdx.x == 0) {
        float t = 0.f;
#pragma unroll
        for (int i = 0; i < 8; i++) t += ws[i];
        out[0] = t * (1.0f / BATCH);
    }
}

extern "C" void kernel_launch(void* const* d_in, const int* in_sizes, int n_in,
                              void* d_out, int out_size) {
    const float* emb = (const float*)d_in[0];
    const int* links = (const int*)d_in[1];

    cudaFuncSetAttribute(k_gram, cudaFuncAttributeMaxDynamicSharedMemorySize, SMEM_TOTAL);

    k_normalize<<<NROWS / 4, 128>>>(emb, links);
    k_gram<<<NB * (NB + 1) / 2, 128, SMEM_TOTAL>>>();
    k_finalize<<<1, 256>>>((float*)d_out);
}

// round 14
// speedup vs baseline: 1.0041x; 1.0041x over previous
#include <cuda_runtime.h>
#include <cuda_bf16.h>
#include <cstdint>
#include <math.h>

// ---- problem constants ----
#define NUM_ENT 100000
#define BATCH   4096
#define NROWS   8192         // 2*BATCH rows of H = [h1; h2]
#define DIM     768
#define NB      64           // NROWS / 128 tile grid
#define NCHUNK  6            // DIM / 128 (128 fp8 elements = 128 B per chunk row)
#define C_OFF   20.0f
#define SCALE_IN 16.0f                    // pre-scale before e4m3 quantization
#define LOGIT_SCALE (20.0f / 256.0f)      // 1/TAU divided by SCALE_IN^2

#define SMSTRIDE 144                 // 128 B data + 16 B pad -> ldmatrix conflict-free
#define TILEBYTES (128 * SMSTRIDE)   // 18432 B per matrix tile
#define BUFBYTES  (2 * TILEBYTES)    // A + B per stage
#define SMEM_TOTAL (2 * BUFBYTES)    // double buffered: 73728 B

// ---- device scratch ----
__device__ __align__(16) uint32_t g_H8[(size_t)NROWS * (DIM / 4)];  // e4m3 rows, 6.3 MB
__device__ float g_S[NROWS];
__device__ float g_D[BATCH];

__device__ __forceinline__ uint32_t smem_u32(const void* p) {
    uint32_t a;
    asm("{ .reg .u64 t; cvta.to.shared.u64 t, %1; cvt.u32.u64 %0, t; }" : "=r"(a) : "l"(p));
    return a;
}
__device__ __forceinline__ uint32_t pack4_e4m3(float e0, float e1, float e2, float e3) {
    uint16_t lo, hi;
    asm("cvt.rn.satfinite.e4m3x2.f32 %0, %1, %2;" : "=h"(lo) : "f"(e1), "f"(e0));
    asm("cvt.rn.satfinite.e4m3x2.f32 %0, %1, %2;" : "=h"(hi) : "f"(e3), "f"(e2));
    return (uint32_t)lo | ((uint32_t)hi << 16);
}
__device__ __forceinline__ void ldsm_x4(uint32_t& r0, uint32_t& r1, uint32_t& r2, uint32_t& r3,
                                        uint32_t addr) {
    asm volatile("ldmatrix.sync.aligned.m8n8.x4.shared.b16 {%0,%1,%2,%3}, [%4];"
                 : "=r"(r0), "=r"(r1), "=r"(r2), "=r"(r3) : "r"(addr));
}
__device__ __forceinline__ void mma_fp8(float* c, const uint32_t* a, uint32_t b0, uint32_t b1) {
    asm volatile(
        "mma.sync.aligned.m16n8k32.row.col.f32.e4m3.e4m3.f32 "
        "{%0,%1,%2,%3}, {%4,%5,%6,%7}, {%8,%9}, {%0,%1,%2,%3};"
        : "+f"(c[0]), "+f"(c[1]), "+f"(c[2]), "+f"(c[3])
        : "r"(a[0]), "r"(a[1]), "r"(a[2]), "r"(a[3]), "r"(b0), "r"(b1));
}
__device__ __forceinline__ void cp16(uint32_t dst, const void* src) {
    asm volatile("cp.async.cg.shared.global [%0], [%1], 16;" :: "r"(dst), "l"(src));
}

// ---------------- K1: warp-per-row gather + L2-normalize -> scaled e4m3 H, zero S ----------------
__global__ void k_normalize(const float* __restrict__ emb,
                            const int* __restrict__ links) {
    const int r = (blockIdx.x << 2) | (threadIdx.x >> 5);   // 4 rows per 128-thread block
    const int lane = threadIdx.x & 31;
    if (threadIdx.x < 4) g_S[(blockIdx.x << 2) + threadIdx.x] = 0.f;  // re-zero each replay

    int ent = (r < BATCH) ? links[2 * r] : links[2 * (r - BATCH) + 1];
    if (ent < 0) ent = 0;
    if (ent >= NUM_ENT) ent = NUM_ENT - 1;
    const float4* src = (const float4*)(emb + (size_t)ent * DIM);  // 192 float4s

    float4 v[6];
    float ss = 0.f;
#pragma unroll
    for (int j = 0; j < 6; j++) {
        v[j] = src[lane + j * 32];
        ss += v[j].x * v[j].x + v[j].y * v[j].y + v[j].z * v[j].z + v[j].w * v[j].w;
    }
#pragma unroll
    for (int o = 16; o; o >>= 1) ss += __shfl_xor_sync(0xffffffffu, ss, o);
    const float inv = rsqrtf(ss) * SCALE_IN;

    uint32_t* dst = g_H8 + (size_t)r * (DIM / 4);
#pragma unroll
    for (int j = 0; j < 6; j++)
        dst[lane + j * 32] = pack4_e4m3(v[j].x * inv, v[j].y * inv, v[j].z * inv, v[j].w * inv);
}

// ---------------- K2: triangular 128x128 tiles, 4 warps x (64x64), fp8 mma ----------------
__global__ void __launch_bounds__(128, 2) k_gram() {
    extern __shared__ __align__(16) char smem[];
    const uint32_t sb = smem_u32(smem);

    // Closed-form linear id -> upper-triangular (bi, bj), bi <= bj < NB.
    const float fidx = (float)blockIdx.x;
    int bi = (int)((2.0f * NB + 1.0f - sqrtf((2.0f * NB + 1.0f) * (2.0f * NB + 1.0f)
                                             - 8.0f * fidx)) * 0.5f);
    if (bi < 0) bi = 0;
    if (bi > NB - 1) bi = NB - 1;
    while (bi > 0 && (int)blockIdx.x < bi * NB - (bi * (bi - 1)) / 2) bi--;
    while (bi < NB - 1 && (int)blockIdx.x >= (bi + 1) * NB - ((bi + 1) * bi) / 2) bi++;
    const int bj = bi + ((int)blockIdx.x - (bi * NB - (bi * (bi - 1)) / 2));

    const int rowBase = bi * 128;
    const int colBase = bj * 128;
    const int tid = threadIdx.x, wid = tid >> 5, lid = tid & 31;
    const int wm = (wid >> 1) * 64;   // warp m-offset (0 or 64)
    const int wn = (wid & 1) * 64;    // warp n-offset (0 or 64)

    const char* gA = (const char*)(g_H8 + (size_t)rowBase * (DIM / 4));  // 768 B per row
    const char* gB = (const char*)(g_H8 + (size_t)colBase * (DIM / 4));

    // per-thread load coords (8 x 16B per matrix per chunk, 128 threads)
    int lrow[8], lq[8];
#pragma unroll
    for (int i = 0; i < 8; i++) {
        int idx = tid + i * 128;       // 0..1023
        lrow[i] = idx >> 3;
        lq[i] = (idx & 7) * 16;
    }

    // prologue: prefetch chunk 0 into buffer 0
#pragma unroll
    for (int i = 0; i < 8; i++) {
        cp16(sb + lrow[i] * SMSTRIDE + lq[i], gA + (size_t)lrow[i] * 768 + lq[i]);
        cp16(sb + TILEBYTES + lrow[i] * SMSTRIDE + lq[i], gB + (size_t)lrow[i] * 768 + lq[i]);
    }
    asm volatile("cp.async.commit_group;" ::: "memory");

    float c[4][8][4];   // [am 16-row][an 8-col][quad]
#pragma unroll
    for (int am = 0; am < 4; am++)
#pragma unroll
        for (int an = 0; an < 8; an++)
#pragma unroll
            for (int q = 0; q < 4; q++) c[am][an][q] = 0.f;

    for (int ch = 0; ch < NCHUNK; ch++) {
        if (ch + 1 < NCHUNK) {
            const uint32_t nb = sb + ((ch + 1) & 1) * BUFBYTES;
            const int off = (ch + 1) * 128;
#pragma unroll
            for (int i = 0; i < 8; i++) {
                cp16(nb + lrow[i] * SMSTRIDE + lq[i],
                     gA + (size_t)lrow[i] * 768 + off + lq[i]);
                cp16(nb + TILEBYTES + lrow[i] * SMSTRIDE + lq[i],
                     gB + (size_t)lrow[i] * 768 + off + lq[i]);
            }
            asm volatile("cp.async.commit_group;" ::: "memory");
            asm volatile("cp.async.wait_group 1;" ::: "memory");
        } else {
            asm volatile("cp.async.wait_group 0;" ::: "memory");
        }
        __syncthreads();  // chunk ch data visible

        const uint32_t sbA = sb + (ch & 1) * BUFBYTES;
        const uint32_t sbB = sbA + TILEBYTES;

#pragma unroll
        for (int kh = 0; kh < 2; kh++) {   // two 64-byte k halves (64 fp8 elements each)
            uint32_t bfr[8][4];
#pragma unroll
            for (int an = 0; an < 8; an++) {
                int n = wn + an * 8 + (lid & 7);
                uint32_t addr = sbB + n * SMSTRIDE + kh * 64 + ((lid >> 3) & 3) * 16;
                ldsm_x4(bfr[an][0], bfr[an][1], bfr[an][2], bfr[an][3], addr);
            }
#pragma unroll
            for (int k2 = 0; k2 < 2; k2++) {  // k32 step = 32 bytes
                uint32_t afr[4][4];
#pragma unroll
                for (int am = 0; am < 4; am++) {
                    int row = wm + am * 16 + (lid & 15);
                    uint32_t addr = sbA + row * SMSTRIDE + (kh * 2 + k2) * 32 + (lid >> 4) * 16;
                    ldsm_x4(afr[am][0], afr[am][1], afr[am][2], afr[am][3], addr);
                }
#pragma unroll
                for (int am = 0; am < 4; am++)
#pragma unroll
                    for (int an = 0; an < 8; an++)
                        mma_fp8(c[am][an], afr[am], bfr[an][k2 * 2], bfr[an][k2 * 2 + 1]);
            }
        }
        __syncthreads();  // all warps done with this buffer before overwrite
    }

    // ---- Epilogue: scale, diag capture, exp (self-excluded), row & col sums ----
    float rs[8];    // row sums: [am*2 + half]
    float cs[16];   // col sums: [an*2 + subcol]
#pragma unroll
    for (int i = 0; i < 8; i++) rs[i] = 0.f;
#pragma unroll
    for (int i = 0; i < 16; i++) cs[i] = 0.f;

#pragma unroll
    for (int am = 0; am < 4; am++) {
        int rG0 = rowBase + wm + am * 16 + (lid >> 2);
#pragma unroll
        for (int an = 0; an < 8; an++) {
            int cG0 = colBase + wn + an * 8 + (lid & 3) * 2;
#pragma unroll
            for (int q = 0; q < 4; q++) {
                int rG = rG0 + (q >> 1) * 8;
                int cG = cG0 + (q & 1);
                float val = c[am][an][q] * LOGIT_SCALE;
                if (cG == rG + BATCH) g_D[rG] = val;  // diag of logits_ab
                float e = (rG == cG) ? 0.f : __expf(val - C_OFF);
                rs[am * 2 + (q >> 1)] += e;
                cs[an * 2 + (q & 1)] += e;
            }
        }
    }

    // Row reduce across the quad (lanes differing in lid&3 hold same rows)
#pragma unroll
    for (int i = 0; i < 8; i++) {
        rs[i] += __shfl_xor_sync(0xffffffffu, rs[i], 1);
        rs[i] += __shfl_xor_sync(0xffffffffu, rs[i], 2);
    }
    if ((lid & 3) == 0) {
#pragma unroll
        for (int am = 0; am < 4; am++)
#pragma unroll
            for (int h = 0; h < 2; h++)
                atomicAdd(&g_S[rowBase + wm + am * 16 + (lid >> 2) + h * 8],
                          rs[am * 2 + h]);
    }

    // Col reduce across groups (lanes differing in lid>>2 hold same cols); symmetry term
    if (bi != bj) {
#pragma unroll
        for (int i = 0; i < 16; i++) {
            cs[i] += __shfl_xor_sync(0xffffffffu, cs[i], 4);
            cs[i] += __shfl_xor_sync(0xffffffffu, cs[i], 8);
            cs[i] += __shfl_xor_sync(0xffffffffu, cs[i], 16);
        }
        if (lid < 4) {
#pragma unroll
            for (int an = 0; an < 8; an++)
#pragma unroll
                for (int s = 0; s < 2; s++)
                    atomicAdd(&g_S[colBase + wn + an * 8 + lid * 2 + s],
                              cs[an * 2 + s]);
        }
    }
}

// ---------------- K3: final loss reduction ----------------
__global__ void k_finalize(float* __restrict__ out) {
    float acc = 0.f;
    for (int i = threadIdx.x; i < BATCH; i += 256) {
        float lse_a = C_OFF + logf(g_S[i]);
        float lse_b = C_OFF + logf(g_S[BATCH + i]);
        acc += 0.5f * (lse_a + lse_b) - g_D[i];  // ALPHA = 0.5
    }
#pragma unroll
    for (int o = 16; o; o >>= 1) acc += __shfl_xor_sync(0xffffffffu, acc, o);
    __shared__ float ws[8];
    if ((threadIdx.x & 31) == 0) ws[threadIdx.x >> 5] = acc;
    __syncthreads();
    if (threadIdx.x == 0) {
        float t = 0.f;
#pragma unroll
        for (int i = 0; i < 8; i++) t += ws[i];
        out[0] = t * (1.0f / BATCH);
    }
}

extern "C" void kernel_launch(void* const* d_in, const int* in_sizes, int n_in,
                              void* d_out, int out_size) {
    const float* emb = (const float*)d_in[0];
    const int* links = (const int*)d_in[1];

    cudaFuncSetAttribute(k_gram, cudaFuncAttributeMaxDynamicSharedMemorySize, SMEM_TOTAL);

    k_normalize<<<NROWS / 4, 128>>>(emb, links);
    k_gram<<<NB * (NB + 1) / 2, 128, SMEM_TOTAL>>>();
    k_finalize<<<1, 256>>>((float*)d_out);
}